// round 6
// baseline (speedup 1.0000x reference)
#include <cuda_runtime.h>
#include <math.h>

#define B_  8
#define L_  2048
#define E_  100
#define FM_ 50
#define Y_  8921
#define K_  9

#define TY  32          // labels per block (attn kernel)
#define LC  256         // l-chunk staged in smem
#define NYT 279         // ceil(Y_/TY)

// scratch (static device arrays are allowed)
__device__ float g_h[(size_t)B_ * FM_ * L_];          // [b][f][l]  3.28 MB
__device__ float g_losspart[B_ * NYT];

// ---- packed f32x2 helpers ------------------------------------------------
__device__ __forceinline__ float2 unpack2(unsigned long long v) {
    float2 f;
    asm("mov.b64 {%0,%1}, %2;" : "=f"(f.x), "=f"(f.y) : "l"(v));
    return f;
}
#define FMA2(d, a, b) \
    asm("fma.rn.f32x2 %0, %1, %2, %0;" : "+l"(d) : "l"(a), "l"(b))

// ---------------------------------------------------------------------------
// Kernel 1: embedding gather + conv1d(K=9, same) + bias + tanh -> g_h[b][f][l]
// ---------------------------------------------------------------------------
__global__ void __launch_bounds__(256) conv_kernel(
    const int* __restrict__ tokens,
    const float* __restrict__ embed_W,
    const float* __restrict__ conv_w,
    const float* __restrict__ conv_b)
{
    __shared__ int   tok_s[72];
    __shared__ float x_s[72][21];          // e-chunk of 20 (pad 21)
    __shared__ float w_s[50][20][9];       // f, e-chunk, k

    const int tid   = threadIdx.x;
    const int b     = blockIdx.y;
    const int lbase = blockIdx.x * 64;

    if (tid < 72) {
        int gl = lbase + tid - 4;
        tok_s[tid] = (gl >= 0 && gl < L_) ? tokens[b * L_ + gl] : -1;
    }
    __syncthreads();

    const int f  = tid >> 2;     // 0..63 (valid < 50)
    const int lg = tid & 3;
    const int l0 = lg * 16;

    float acc[16];
#pragma unroll
    for (int j = 0; j < 16; j++) acc[j] = 0.f;

    for (int ec = 0; ec < 5; ec++) {
        for (int idx = tid; idx < 72 * 20; idx += 256) {
            int i = idx / 20, e = idx % 20;
            int t = tok_s[i];
            x_s[i][e] = (t >= 0) ? embed_W[(size_t)t * E_ + ec * 20 + e] : 0.f;
        }
        for (int idx = tid; idx < 50 * 20 * 9; idx += 256) {
            int ff = idx / 180, r = idx % 180;
            w_s[ff][r / 9][r % 9] = conv_w[ff * (E_ * K_) + ec * 180 + r];
        }
        __syncthreads();

        if (f < FM_) {
            for (int e = 0; e < 20; e++) {
                float xv[24];
#pragma unroll
                for (int t = 0; t < 24; t++) xv[t] = x_s[l0 + t][e];
                float wv[9];
#pragma unroll
                for (int k = 0; k < 9; k++) wv[k] = w_s[f][e][k];
#pragma unroll
                for (int k = 0; k < 9; k++)
#pragma unroll
                    for (int j = 0; j < 16; j++)
                        acc[j] += xv[j + k] * wv[k];
            }
        }
        __syncthreads();
    }

    if (f < FM_) {
        float bias = conv_b[f];
#pragma unroll
        for (int j = 0; j < 16; j++) {
            int l = lbase + l0 + j;
            g_h[((size_t)(b * FM_) + f) * L_ + l] = tanhf(acc[j] + bias);
        }
    }
}

// ---------------------------------------------------------------------------
// Kernel 2: fused label-attention.
// block = (y-tile of 32, b), 512 threads = 16 warps (2 CTAs/SM, 32 warps/SM).
// warp w: label group lg = w&7 (4 labels), position half ph = w>>3 (128 pos).
// pass1: S,Q via FFMA2; e=exp(s) streamed to alpha gmem (SCALAR stores —
//        alpha region is only 4-byte aligned); Z+=e; R+=e*q.
// tail:  iZ per label; block rescales its own alpha rows (L2-hot) in place.
// ---------------------------------------------------------------------------
__global__ void __launch_bounds__(512, 2) attn_kernel(
    const float* __restrict__ U_w,
    const float* __restrict__ final_w,
    const float* __restrict__ final_b,
    const float* __restrict__ target,
    float* __restrict__ out_yhat,
    float* __restrict__ out_alpha,
    int write_alpha)
{
    extern __shared__ __align__(16) unsigned char smraw[];
    float4* u_d4   = (float4*)smraw;              // FM_*16 = 800 float4
    float4* f_d4   = u_d4 + FM_ * 16;             // 800 float4
    float*  h_s    = (float*)(f_d4 + FM_ * 16);   // FM_*LC = 12800 floats
    float*  zr_s   = h_s + FM_ * LC;              // 128
    float*  iZ_s   = zr_s + 128;                  // 32
    float*  loss_s = iZ_s + TY;                   // 32

    const int tid  = threadIdx.x;
    const int lane = tid & 31;
    const int warp = tid >> 5;
    const int b    = blockIdx.y;
    const int y0t  = blockIdx.x * TY;

    const int lg  = warp & 7;         // label group -> yl0 = 4*lg
    const int ph  = warp >> 3;        // position half (0/1)
    const int yl0 = lg * 4;
    const int pbase = ph * 128 + 2 * lane;

    // stage duplicated weights: u_d4[f*16+j] = {u[2j],u[2j],u[2j+1],u[2j+1]}
    for (int idx = tid; idx < FM_ * 16; idx += 512) {
        int f = idx >> 4, j = idx & 15;
        int gy0 = y0t + 2 * j, gy1 = gy0 + 1;
        float u0 = (gy0 < Y_) ? U_w[gy0 * FM_ + f] : 0.f;
        float u1 = (gy1 < Y_) ? U_w[gy1 * FM_ + f] : 0.f;
        u_d4[idx] = make_float4(u0, u0, u1, u1);
        float v0 = (gy0 < Y_) ? final_w[gy0 * FM_ + f] : 0.f;
        float v1 = (gy1 < Y_) ? final_w[gy1 * FM_ + f] : 0.f;
        f_d4[idx] = make_float4(v0, v0, v1, v1);
    }

    float Zacc[4] = {0.f, 0.f, 0.f, 0.f};
    float Racc[4] = {0.f, 0.f, 0.f, 0.f};

    const size_t arow = (size_t)b * Y_ + y0t;   // first label row of this block

    for (int ch = 0; ch < L_ / LC; ch++) {
        const int lb = ch * LC;
        __syncthreads();   // previous chunk readers done (covers weight staging)
        // stage h chunk: g_h[b][f][lb..lb+255]  (float4, fully coalesced)
        {
            const float4* gsrc =
                (const float4*)(g_h + (size_t)b * FM_ * L_ + lb);
            float4* dst = (float4*)h_s;
            for (int idx = tid; idx < FM_ * LC / 4; idx += 512) {
                int f = idx >> 6, v = idx & 63;       // 64 float4 per f-row
                dst[(f << 6) + v] = gsrc[(size_t)f * (L_ / 4) + v];
            }
        }
        __syncthreads();

        unsigned long long S[4][2] = {{0,0},{0,0},{0,0},{0,0}};
        unsigned long long Q[4][2] = {{0,0},{0,0},{0,0},{0,0}};

        const float*      hp = h_s + pbase;
        const ulonglong2* up = (const ulonglong2*)(u_d4) + lg * 2;
        const ulonglong2* fp = (const ulonglong2*)(f_d4) + lg * 2;

#pragma unroll 2
        for (int f = 0; f < FM_; f++) {
            unsigned long long h0 = *(const unsigned long long*)(hp);
            unsigned long long h1 = *(const unsigned long long*)(hp + 64);
            ulonglong2 ua = up[0];   // labels yl0, yl0+1 (dup-packed)
            ulonglong2 ub = up[1];   // labels yl0+2, yl0+3
            ulonglong2 fa = fp[0];
            ulonglong2 fb = fp[1];
            FMA2(S[0][0], h0, ua.x); FMA2(S[0][1], h1, ua.x);
            FMA2(S[1][0], h0, ua.y); FMA2(S[1][1], h1, ua.y);
            FMA2(S[2][0], h0, ub.x); FMA2(S[2][1], h1, ub.x);
            FMA2(S[3][0], h0, ub.y); FMA2(S[3][1], h1, ub.y);
            FMA2(Q[0][0], h0, fa.x); FMA2(Q[0][1], h1, fa.x);
            FMA2(Q[1][0], h0, fa.y); FMA2(Q[1][1], h1, fa.y);
            FMA2(Q[2][0], h0, fb.x); FMA2(Q[2][1], h1, fb.x);
            FMA2(Q[3][0], h0, fb.y); FMA2(Q[3][1], h1, fb.y);
            hp += LC; up += 16; fp += 16;
        }

        // per-chunk epilogue: e = exp(s) -> gmem (unnormalized, SCALAR stores)
#pragma unroll
        for (int i = 0; i < 4; i++) {
            const int gy = y0t + yl0 + i;
            float* abase = out_alpha + (arow + yl0 + i) * L_ + lb + pbase;
#pragma unroll
            for (int p = 0; p < 2; p++) {
                float2 s = unpack2(S[i][p]);
                float2 q = unpack2(Q[i][p]);
                float e0 = __expf(s.x), e1 = __expf(s.y);
                Zacc[i] += e0 + e1;
                Racc[i] += e0 * q.x + e1 * q.y;
                if (write_alpha && gy < Y_) {
                    abase[p * 64 + 0] = e0;
                    abase[p * 64 + 1] = e1;
                }
            }
        }
    }

    // lane reduction of Z,R
#pragma unroll
    for (int o = 16; o > 0; o >>= 1) {
#pragma unroll
        for (int i = 0; i < 4; i++) {
            Zacc[i] += __shfl_xor_sync(0xffffffffu, Zacc[i], o);
            Racc[i] += __shfl_xor_sync(0xffffffffu, Racc[i], o);
        }
    }
    if (lane == 0) {
#pragma unroll
        for (int i = 0; i < 4; i++) {
            zr_s[(warp * 4 + i) * 2 + 0] = Zacc[i];
            zr_s[(warp * 4 + i) * 2 + 1] = Racc[i];
        }
    }
    __syncthreads();

    // finalize per label: combine the two position-half warps
    if (tid < TY) {
        int y = tid;
        int g = y >> 2, i = y & 3;
        float Z = zr_s[(g * 4 + i) * 2 + 0] + zr_s[((g + 8) * 4 + i) * 2 + 0];
        float R = zr_s[(g * 4 + i) * 2 + 1] + zr_s[((g + 8) * 4 + i) * 2 + 1];
        iZ_s[y] = 1.f / Z;
        float lossterm = 0.f;
        int gy = y0t + y;
        if (gy < Y_) {
            float r  = R / Z + final_b[gy];
            float yh = 1.f / (1.f + expf(-r));
            out_yhat[b * Y_ + gy] = yh;
            float t = target[b * Y_ + gy];
            lossterm = t * logf(yh + 1e-12f) + (1.f - t) * logf(1.f - yh + 1e-12f);
        }
        loss_s[y] = lossterm;
    }
    __syncthreads();
    if (tid == 0) {
        float s = 0.f;
#pragma unroll
        for (int i = 0; i < TY; i++) s += loss_s[i];
        g_losspart[b * gridDim.x + blockIdx.x] = s;
    }

    // in-place rescale: block's alpha rows are still L2-hot. SCALAR accesses
    // (alpha region is only 4-byte aligned).
    if (write_alpha) {
#pragma unroll 1
        for (int y = 0; y < TY; y++) {
            int gy = y0t + y;
            if (gy >= Y_) break;
            float iZ = iZ_s[y];
            float* ap = out_alpha + (arow + y) * L_;
#pragma unroll 4
            for (int v = tid; v < L_; v += 512)
                ap[v] *= iZ;
        }
    }
}

// ---------------------------------------------------------------------------
// Kernel 3: deterministic loss reduction
// ---------------------------------------------------------------------------
__global__ void loss_kernel(float* __restrict__ out_loss, int npart)
{
    __shared__ float red[256];
    float s = 0.f;
    for (int i = threadIdx.x; i < npart; i += 256) s += g_losspart[i];
    red[threadIdx.x] = s;
    __syncthreads();
    for (int o = 128; o > 0; o >>= 1) {
        if (threadIdx.x < o) red[threadIdx.x] += red[threadIdx.x + o];
        __syncthreads();
    }
    if (threadIdx.x == 0) *out_loss = -red[0] / (float)(B_ * Y_);
}

// ---------------------------------------------------------------------------
extern "C" void kernel_launch(void* const* d_in, const int* in_sizes, int n_in,
                              void* d_out, int out_size)
{
    const int*   tokens  = (const int*)  d_in[0];
    const float* target  = (const float*)d_in[1];
    const float* embed_W = (const float*)d_in[2];
    const float* conv_w  = (const float*)d_in[3];
    const float* conv_b  = (const float*)d_in[4];
    const float* U_w     = (const float*)d_in[5];
    const float* final_w = (const float*)d_in[6];
    const float* final_b = (const float*)d_in[7];
    float* out = (float*)d_out;

    const long long yhat_n  = (long long)B_ * Y_;                 // 71368
    const long long total_n = yhat_n + 1 + (long long)B_ * Y_ * L_;
    int write_loss  = (out_size >= (int)(yhat_n + 1)) ? 1 : 0;
    int write_alpha = ((long long)out_size >= total_n) ? 1 : 0;

    const int smem_bytes = (2 * FM_ * 16) * 16 +
                           (FM_ * LC + 128 + TY + TY) * 4;   // ~77.6 KB
    cudaFuncSetAttribute(attn_kernel, cudaFuncAttributeMaxDynamicSharedMemorySize,
                         smem_bytes);

    conv_kernel<<<dim3(L_ / 64, B_), 256>>>(tokens, embed_W, conv_w, conv_b);

    float* out_alpha = out + yhat_n + 1;
    attn_kernel<<<dim3(NYT, B_), 512, smem_bytes>>>(
        U_w, final_w, final_b, target, out, out_alpha, write_alpha);

    if (write_loss)
        loss_kernel<<<1, 256>>>(out + yhat_n, B_ * NYT);
}

// round 8
// speedup vs baseline: 1.1329x; 1.1329x over previous
#include <cuda_runtime.h>
#include <math.h>

#define B_  8
#define L_  2048
#define E_  100
#define FM_ 50
#define Y_  8921
#define K_  9

#define TY  32          // labels per block (attn kernel): 8 warps x 4 labels
#define LC  128         // l-chunk staged in smem (shared by all warps)
#define NYT 279         // ceil(Y_/TY)
#define WROW (TY / 2)   // one f-row of dup-packed weights, in 16-byte units (=16)

// scratch (static device arrays are allowed)
__device__ float g_h[(size_t)B_ * FM_ * L_];          // [b][f][l]  3.28 MB
__device__ float g_losspart[B_ * NYT];

// ---- packed f32x2 helpers ------------------------------------------------
__device__ __forceinline__ float2 unpack2(unsigned long long v) {
    float2 f;
    asm("mov.b64 {%0,%1}, %2;" : "=f"(f.x), "=f"(f.y) : "l"(v));
    return f;
}
#define FMA2(d, a, b) \
    asm("fma.rn.f32x2 %0, %1, %2, %0;" : "+l"(d) : "l"(a), "l"(b))

// ---------------------------------------------------------------------------
// Kernel 1: embedding gather + conv1d(K=9, same) + bias + tanh -> g_h[b][f][l]
// ---------------------------------------------------------------------------
__global__ void __launch_bounds__(256) conv_kernel(
    const int* __restrict__ tokens,
    const float* __restrict__ embed_W,
    const float* __restrict__ conv_w,
    const float* __restrict__ conv_b)
{
    __shared__ int   tok_s[72];
    __shared__ float x_s[72][21];          // e-chunk of 20 (pad 21)
    __shared__ float w_s[50][20][9];       // f, e-chunk, k

    const int tid   = threadIdx.x;
    const int b     = blockIdx.y;
    const int lbase = blockIdx.x * 64;

    if (tid < 72) {
        int gl = lbase + tid - 4;
        tok_s[tid] = (gl >= 0 && gl < L_) ? tokens[b * L_ + gl] : -1;
    }
    __syncthreads();

    const int f  = tid >> 2;     // 0..63 (valid < 50)
    const int lg = tid & 3;
    const int l0 = lg * 16;

    float acc[16];
#pragma unroll
    for (int j = 0; j < 16; j++) acc[j] = 0.f;

    for (int ec = 0; ec < 5; ec++) {
        for (int idx = tid; idx < 72 * 20; idx += 256) {
            int i = idx / 20, e = idx % 20;
            int t = tok_s[i];
            x_s[i][e] = (t >= 0) ? embed_W[(size_t)t * E_ + ec * 20 + e] : 0.f;
        }
        for (int idx = tid; idx < 50 * 20 * 9; idx += 256) {
            int ff = idx / 180, r = idx % 180;
            w_s[ff][r / 9][r % 9] = conv_w[ff * (E_ * K_) + ec * 180 + r];
        }
        __syncthreads();

        if (f < FM_) {
            for (int e = 0; e < 20; e++) {
                float xv[24];
#pragma unroll
                for (int t = 0; t < 24; t++) xv[t] = x_s[l0 + t][e];
                float wv[9];
#pragma unroll
                for (int k = 0; k < 9; k++) wv[k] = w_s[f][e][k];
#pragma unroll
                for (int k = 0; k < 9; k++)
#pragma unroll
                    for (int j = 0; j < 16; j++)
                        acc[j] += xv[j + k] * wv[k];
            }
        }
        __syncthreads();
    }

    if (f < FM_) {
        float bias = conv_b[f];
#pragma unroll
        for (int j = 0; j < 16; j++) {
            int l = lbase + l0 + j;
            g_h[((size_t)(b * FM_) + f) * L_ + l] = tanhf(acc[j] + bias);
        }
    }
}

// ---------------------------------------------------------------------------
// Kernel 2: fused label-attention.
// block = (y-tile of 32, b), 256 threads = 8 warps, 3 CTAs/SM (24 warps/SM).
// ALL warps share the same 128-position chunk; warp w owns labels 4w..4w+3.
// Each label's Z,R is warp-local -> no cross-warp combine, no tail barrier.
// Weight layout: u_d4[f*WROW + j] = {u[2j],u[2j],u[2j+1],u[2j+1]}, WROW=16
// 16-byte entries per f-row; inner-loop cursor stride is WROW (layout-derived).
// pass1: S,Q via FFMA2; e=exp(s) streamed to alpha gmem (SCALAR stores —
//        alpha region is only 4-byte aligned); Z+=e; R+=e*q.
// tail:  butterfly-reduce Z,R in-warp; rescale own 4 rows (L2-hot) in place.
// ---------------------------------------------------------------------------
__global__ void __launch_bounds__(256, 3) attn_kernel(
    const float* __restrict__ U_w,
    const float* __restrict__ final_w,
    const float* __restrict__ final_b,
    const float* __restrict__ target,
    float* __restrict__ out_yhat,
    float* __restrict__ out_alpha,
    int write_alpha)
{
    __shared__ float  h_s[FM_ * LC];        // 25.6 KB, row stride 128
    __shared__ float4 u_d4[FM_ * WROW];     // dup-packed U:    12.8 KB
    __shared__ float4 f_d4[FM_ * WROW];     // dup-packed final 12.8 KB
    __shared__ float  loss_s[8];

    const int tid  = threadIdx.x;
    const int lane = tid & 31;
    const int warp = tid >> 5;
    const int b    = blockIdx.y;
    const int y0t  = blockIdx.x * TY;

    const int yl0   = warp * 4;       // warp's first label within tile
    const int pbase = 2 * lane;       // position base within 128-chunk

    // stage duplicated weights: u_d4[f*WROW+j] = {u[2j],u[2j],u[2j+1],u[2j+1]}
    for (int idx = tid; idx < FM_ * WROW; idx += 256) {
        int f = idx / WROW, j = idx % WROW;
        int gy0 = y0t + 2 * j, gy1 = gy0 + 1;
        float u0 = (gy0 < Y_) ? U_w[gy0 * FM_ + f] : 0.f;
        float u1 = (gy1 < Y_) ? U_w[gy1 * FM_ + f] : 0.f;
        u_d4[idx] = make_float4(u0, u0, u1, u1);
        float v0 = (gy0 < Y_) ? final_w[gy0 * FM_ + f] : 0.f;
        float v1 = (gy1 < Y_) ? final_w[gy1 * FM_ + f] : 0.f;
        f_d4[idx] = make_float4(v0, v0, v1, v1);
    }

    float Zacc[4] = {0.f, 0.f, 0.f, 0.f};
    float Racc[4] = {0.f, 0.f, 0.f, 0.f};

    const size_t arow = (size_t)b * Y_ + y0t;   // first label row of this block

    for (int ch = 0; ch < L_ / LC; ch++) {
        const int lb = ch * LC;
        __syncthreads();   // previous chunk readers done (covers weight staging)
        // stage h chunk: g_h[b][f][lb..lb+127]  (float4, fully coalesced)
        {
            const float4* gsrc =
                (const float4*)(g_h + (size_t)b * FM_ * L_ + lb);
            float4* dst = (float4*)h_s;
            for (int idx = tid; idx < FM_ * LC / 4; idx += 256) {
                int f = idx >> 5, v = idx & 31;       // 32 float4 per f-row
                dst[(f << 5) + v] = gsrc[(size_t)f * (L_ / 4) + v];
            }
        }
        __syncthreads();

        unsigned long long S[4][2] = {{0,0},{0,0},{0,0},{0,0}};
        unsigned long long Q[4][2] = {{0,0},{0,0},{0,0},{0,0}};

        const float*      hp = h_s + pbase;
        // warp's 2 entries within each f-row; advance by WROW entries per f
        const ulonglong2* up = (const ulonglong2*)(u_d4) + warp * 2;
        const ulonglong2* fp = (const ulonglong2*)(f_d4) + warp * 2;

#pragma unroll 2
        for (int f = 0; f < FM_; f++) {
            unsigned long long h0 = *(const unsigned long long*)(hp);
            unsigned long long h1 = *(const unsigned long long*)(hp + 64);
            ulonglong2 ua = up[0];   // labels yl0, yl0+1 (dup-packed)
            ulonglong2 ub = up[1];   // labels yl0+2, yl0+3
            ulonglong2 fa = fp[0];
            ulonglong2 fb = fp[1];
            FMA2(S[0][0], h0, ua.x); FMA2(S[0][1], h1, ua.x);
            FMA2(S[1][0], h0, ua.y); FMA2(S[1][1], h1, ua.y);
            FMA2(S[2][0], h0, ub.x); FMA2(S[2][1], h1, ub.x);
            FMA2(S[3][0], h0, ub.y); FMA2(S[3][1], h1, ub.y);
            FMA2(Q[0][0], h0, fa.x); FMA2(Q[0][1], h1, fa.x);
            FMA2(Q[1][0], h0, fa.y); FMA2(Q[1][1], h1, fa.y);
            FMA2(Q[2][0], h0, fb.x); FMA2(Q[2][1], h1, fb.x);
            FMA2(Q[3][0], h0, fb.y); FMA2(Q[3][1], h1, fb.y);
            hp += LC; up += WROW; fp += WROW;
        }

        // per-chunk epilogue: e = exp(s) -> gmem (unnormalized, SCALAR stores)
#pragma unroll
        for (int i = 0; i < 4; i++) {
            const int gy = y0t + yl0 + i;
            float* abase = out_alpha + (arow + yl0 + i) * L_ + lb + pbase;
#pragma unroll
            for (int p = 0; p < 2; p++) {
                float2 s = unpack2(S[i][p]);
                float2 q = unpack2(Q[i][p]);
                float e0 = __expf(s.x), e1 = __expf(s.y);
                Zacc[i] += e0 + e1;
                Racc[i] += e0 * q.x + e1 * q.y;
                if (write_alpha && gy < Y_) {
                    abase[p * 64 + 0] = e0;
                    abase[p * 64 + 1] = e1;
                }
            }
        }
    }

    // butterfly reduction: every lane ends with full Z,R for the warp's labels
#pragma unroll
    for (int o = 16; o > 0; o >>= 1) {
#pragma unroll
        for (int i = 0; i < 4; i++) {
            Zacc[i] += __shfl_xor_sync(0xffffffffu, Zacc[i], o);
            Racc[i] += __shfl_xor_sync(0xffffffffu, Racc[i], o);
        }
    }

    // yhat + BCE terms for the warp's 4 labels (lane 0)
    if (lane == 0) {
        float lsum = 0.f;
#pragma unroll
        for (int i = 0; i < 4; i++) {
            int gy = y0t + yl0 + i;
            if (gy < Y_) {
                float r  = Racc[i] / Zacc[i] + final_b[gy];
                float yh = 1.f / (1.f + expf(-r));
                out_yhat[b * Y_ + gy] = yh;
                float t = target[b * Y_ + gy];
                lsum += t * logf(yh + 1e-12f) +
                        (1.f - t) * logf(1.f - yh + 1e-12f);
            }
        }
        loss_s[warp] = lsum;
    }

    // in-place rescale of the warp's own 4 alpha rows (L2-hot). No barrier
    // needed: this warp wrote those rows itself. SCALAR accesses (4B align).
    if (write_alpha) {
#pragma unroll
        for (int i = 0; i < 4; i++) {
            int gy = y0t + yl0 + i;
            if (gy >= Y_) continue;
            float iZ = 1.f / Zacc[i];
            float* ap = out_alpha + (arow + yl0 + i) * L_;
#pragma unroll 4
            for (int v = lane; v < L_; v += 32)
                ap[v] *= iZ;
        }
    }

    __syncthreads();
    if (tid == 0) {
        float s = 0.f;
#pragma unroll
        for (int i = 0; i < 8; i++) s += loss_s[i];
        g_losspart[b * gridDim.x + blockIdx.x] = s;
    }
}

// ---------------------------------------------------------------------------
// Kernel 3: deterministic loss reduction
// ---------------------------------------------------------------------------
__global__ void loss_kernel(float* __restrict__ out_loss, int npart)
{
    __shared__ float red[256];
    float s = 0.f;
    for (int i = threadIdx.x; i < npart; i += 256) s += g_losspart[i];
    red[threadIdx.x] = s;
    __syncthreads();
    for (int o = 128; o > 0; o >>= 1) {
        if (threadIdx.x < o) red[threadIdx.x] += red[threadIdx.x + o];
        __syncthreads();
    }
    if (threadIdx.x == 0) *out_loss = -red[0] / (float)(B_ * Y_);
}

// ---------------------------------------------------------------------------
extern "C" void kernel_launch(void* const* d_in, const int* in_sizes, int n_in,
                              void* d_out, int out_size)
{
    const int*   tokens  = (const int*)  d_in[0];
    const float* target  = (const float*)d_in[1];
    const float* embed_W = (const float*)d_in[2];
    const float* conv_w  = (const float*)d_in[3];
    const float* conv_b  = (const float*)d_in[4];
    const float* U_w     = (const float*)d_in[5];
    const float* final_w = (const float*)d_in[6];
    const float* final_b = (const float*)d_in[7];
    float* out = (float*)d_out;

    const long long yhat_n  = (long long)B_ * Y_;                 // 71368
    const long long total_n = yhat_n + 1 + (long long)B_ * Y_ * L_;
    int write_loss  = (out_size >= (int)(yhat_n + 1)) ? 1 : 0;
    int write_alpha = ((long long)out_size >= total_n) ? 1 : 0;

    conv_kernel<<<dim3(L_ / 64, B_), 256>>>(tokens, embed_W, conv_w, conv_b);

    float* out_alpha = out + yhat_n + 1;
    attn_kernel<<<dim3(NYT, B_), 256>>>(
        U_w, final_w, final_b, target, out, out_alpha, write_alpha);

    if (write_loss)
        loss_kernel<<<1, 256>>>(out + yhat_n, B_ * NYT);
}